// round 2
// baseline (speedup 1.0000x reference)
#include <cuda_runtime.h>
#include <cuda_bf16.h>

// Problem geometry: [B=4, 1, D=160, H=160, W=160]
#define NB 4
#define S  160
#define PLANE      (S * S)          // 25600 elems per (b,d) plane
#define PLANE4     (PLANE / 4)      // 6400 float4/int4 per plane
#define HALF4      (PLANE4 / 2)     // 3200
#define NPLANES    (NB * S)         // 640
#define TOTAL_ELEMS (4.0 * 160.0 * 160.0 * 160.0)

// ---- device scratch (no allocations allowed) ----
__device__ unsigned char g_any[NB][3][S];  // axis projections: 0=D,1=H,2=W
__device__ int      g_lo[NB][3];
__device__ int      g_hi[NB][3];
__device__ int      g_fg[NB];
__device__ double   g_acc;
__device__ unsigned g_done;

// ---------------- kernel 0: zero scratch (every replay) ----------------
__global__ void k_init() {
    int t = blockIdx.x * blockDim.x + threadIdx.x;
    if (t == 0) { g_acc = 0.0; g_done = 0u; }
    if (t < NB * 3 * S) ((unsigned char*)g_any)[t] = 0;
}

// ---------------- kernel 1: mask -> axis projections ----------------
// One block per (b,d) plane, 320 threads. Thread owns a FIXED int4-column
// c = tid%40 and row-group r = tid/40 (8 groups x 20 rows). The W-axis OR
// lives in registers (colOr); only a single conditional byte store per 16B
// load feeds the H-axis flags. Global flag stores are benign races (all 1s).
__global__ __launch_bounds__(320) void k_proj(const int* __restrict__ mask) {
    __shared__ int4 sCol[8][40];
    __shared__ unsigned char sH[S];

    const int bx  = blockIdx.x;          // 0..639
    const int b   = bx / S;
    const int d   = bx - b * S;
    const int tid = threadIdx.x;
    const int c   = tid % 40;
    const int r   = tid / 40;            // 0..7

    if (tid < S) sH[tid] = 0;
    __syncthreads();

    const int4* M = (const int4*)mask + (size_t)bx * PLANE4;

    int4 colOr = make_int4(0, 0, 0, 0);
    #pragma unroll 5
    for (int k = 0; k < 20; k++) {
        int h  = r + k * 8;
        int4 v = M[h * 40 + c];
        colOr.x |= v.x; colOr.y |= v.y; colOr.z |= v.z; colOr.w |= v.w;
        if (v.x | v.y | v.z | v.w) sH[h] = 1;
    }
    sCol[r][c] = colOr;
    int planeAny = __syncthreads_or(colOr.x | colOr.y | colOr.z | colOr.w);

    if (tid < 40) {
        int4 o = sCol[0][tid];
        #pragma unroll
        for (int r2 = 1; r2 < 8; r2++) {
            int4 v = sCol[r2][tid];
            o.x |= v.x; o.y |= v.y; o.z |= v.z; o.w |= v.w;
        }
        if (o.x) g_any[b][2][tid * 4 + 0] = 1;
        if (o.y) g_any[b][2][tid * 4 + 1] = 1;
        if (o.z) g_any[b][2][tid * 4 + 2] = 1;
        if (o.w) g_any[b][2][tid * 4 + 3] = 1;
    }
    if (tid < S && sH[tid]) g_any[b][1][tid] = 1;
    if (tid == 0 && planeAny) g_any[b][0][d] = 1;
}

// ---------------- kernel 2: projections -> bbox (exact f32 reference math) --
__global__ void k_bbox() {
    int t = threadIdx.x;                 // one thread per (b, axis)
    if (t >= NB * 3) return;
    int b  = t / 3;
    int ax = t - b * 3;

    int mn = -1, mx = -1;
    for (int i = 0; i < S; i++) {
        if (g_any[b][ax][i]) { if (mn < 0) mn = i; mx = i; }
    }
    int fg = (mn >= 0);
    if (ax == 0) g_fg[b] = fg;

    int lo = 0, hi = 0;
    if (fg) {
        float mnf = (float)mn, mxf = (float)mx;
        float ctr = (mxf + mnf) * 0.5f;
        float e   = (mxf - mnf + 1.0f) * 0.5f * 1.2f;     // EXPAND
        lo = (int)fmaxf(0.0f, floorf(ctr - e));
        hi = (int)fminf((float)(S - 1), floorf(ctr + e)); // EXCLUSIVE bound
    }
    g_lo[b][ax] = lo;
    g_hi[b][ax] = hi;
}

// ---------------- kernel 3: weighted SSE reduction + finalize ----------------
// 1280 blocks x 320 threads; each block streams half a plane (3200 float4,
// exactly 10 iterations). Last block to finish writes the mean.
__global__ __launch_bounds__(320) void k_main(const float* __restrict__ pred,
                                              const float* __restrict__ truth,
                                              float* __restrict__ out) {
    const int bx    = blockIdx.x;        // 0..1279
    const int plane = bx >> 1;
    const int half  = bx & 1;
    const int b     = plane / S;
    const int d     = plane - b * S;
    const int tid   = threadIdx.x;

    const int fg  = g_fg[b];
    const int loD = g_lo[b][0], hiD = g_hi[b][0];
    const int loH = g_lo[b][1], hiH = g_hi[b][1];
    const int loW = g_lo[b][2], hiW = g_hi[b][2];
    const bool inD = fg && (d >= loD) && (d < hiD);
    const unsigned hRange = (unsigned)(hiH - loH);
    const unsigned wRange = (unsigned)(hiW - loW);

    const float4* P = (const float4*)pred  + (size_t)plane * PLANE4 + half * HALF4;
    const float4* T = (const float4*)truth + (size_t)plane * PLANE4 + half * HALF4;
    const int jbase = half * HALF4;

    float acc = 0.0f;
    #pragma unroll 5
    for (int k = 0; k < 10; k++) {
        int i = tid + k * 320;
        float4 p = P[i];
        float4 t = T[i];
        int j  = jbase + i;
        int h  = j / 40;
        int w0 = (j - h * 40) * 4;
        bool inH = inD && ((unsigned)(h - loH) < hRange);

        float wx = (inH && (unsigned)(w0 + 0 - loW) < wRange) ? 1.0f : 0.01f;
        float wy = (inH && (unsigned)(w0 + 1 - loW) < wRange) ? 1.0f : 0.01f;
        float wz = (inH && (unsigned)(w0 + 2 - loW) < wRange) ? 1.0f : 0.01f;
        float ww = (inH && (unsigned)(w0 + 3 - loW) < wRange) ? 1.0f : 0.01f;

        float dx = p.x - t.x, dy = p.y - t.y, dz = p.z - t.z, dw = p.w - t.w;
        acc += wx * dx * dx;
        acc += wy * dy * dy;
        acc += wz * dz * dz;
        acc += ww * dw * dw;
    }

    // warp reduce (float), then block reduce (double), one atomicAdd per block
    #pragma unroll
    for (int off = 16; off > 0; off >>= 1)
        acc += __shfl_xor_sync(0xFFFFFFFFu, acc, off);

    __shared__ double warpSum[10];
    int lane = tid & 31, wid = tid >> 5;
    if (lane == 0) warpSum[wid] = (double)acc;
    __syncthreads();
    if (tid == 0) {
        double s = 0.0;
        #pragma unroll
        for (int w = 0; w < 10; w++) s += warpSum[w];
        atomicAdd(&g_acc, s);
        __threadfence();
        unsigned ticket = atomicAdd(&g_done, 1u);
        if (ticket == gridDim.x - 1) {
            out[0] = (float)(g_acc / TOTAL_ELEMS);
        }
    }
}

extern "C" void kernel_launch(void* const* d_in, const int* in_sizes, int n_in,
                              void* d_out, int out_size) {
    const float* y_pred = (const float*)d_in[0];
    const float* y_true = (const float*)d_in[1];
    const int*   mask   = (const int*)d_in[2];
    float* out = (float*)d_out;

    k_init<<<2, 1024>>>();
    k_proj<<<NPLANES, 320>>>(mask);
    k_bbox<<<1, 32>>>();
    k_main<<<2 * NPLANES, 320>>>(y_pred, y_true, out);
}